// round 5
// baseline (speedup 1.0000x reference)
#include <cuda_runtime.h>
#include <math.h>
#include <stddef.h>

#define H      128
#define G4     512           // 4*H
#define T_OBS  8
#define PRED   12
#define NNB    64
#define EMB    32
#define NCELL  16            // 4x4 grid cells actually reachable after clamp
#define KF     18            // small-feature dims: [obs/prev(2) | counts(16)]
#define KX     148           // padded x / weight row length: 128 + 18 + 2 pad
#define BT     32            // batch rows per CTA
#define THREADS_R 128
#define BMAX   16384

// ---------------- device scratch (static: no allocations allowed) ----------------
__device__ __align__(128) float g_Wcomb[G4 * KX];      // folded weights, 303 KB
__device__ __align__(128) float g_bias[2 * G4];        // [0:512]=obs bias, [512:1024]=pred bias
__device__ __align__(128) float g_feat[BMAX * T_OBS * KF]; // per (b,t): [obs_x,obs_y,counts0..15]

__device__ __forceinline__ float sigf(float x) { return 1.0f / (1.0f + __expf(-x)); }

// ---------------- kernel 1: fold weights ----------------
// gates = x@W_ih^T + b_ih + h@W_hh^T + b_hh, x=[agent,social]
// agent = obs@W_in^T + b_in ; social = pooled@W_sp^T + b_sp ; pooled = embed^T @ counts
// => gates[g] = sum_k h[k]*W_hh[g,k] + sum_d obs[d]*A[g,d] + sum_c counts[c]*D[g,c] + bias
__global__ void prep_kernel(const float* __restrict__ W_in, const float* __restrict__ b_in,
                            const float* __restrict__ W_sp, const float* __restrict__ b_sp,
                            const float* __restrict__ W_ih, const float* __restrict__ W_hh,
                            const float* __restrict__ b_ih, const float* __restrict__ b_hh,
                            const float* __restrict__ embed)
{
    int g = blockIdx.x * blockDim.x + threadIdx.x;
    if (g >= G4) return;
    const float* wih = W_ih + (size_t)g * 256;   // W_ih row g: [agent(128) | social(128)]
    const float* whh = W_hh + (size_t)g * H;
    float* row = g_Wcomb + (size_t)g * KX;

    #pragma unroll 4
    for (int k = 0; k < H; k++) row[k] = whh[k];

    float a0 = 0.f, a1 = 0.f, s1 = 0.f, s2 = 0.f;
    float C[EMB];
    #pragma unroll
    for (int e = 0; e < EMB; e++) C[e] = 0.f;

    for (int j = 0; j < H; j++) {
        float w1 = wih[j];
        float w2 = wih[H + j];
        a0 += w1 * W_in[j * 2 + 0];
        a1 += w1 * W_in[j * 2 + 1];
        s1 += w1 * b_in[j];
        s2 += w2 * b_sp[j];
        #pragma unroll
        for (int e = 0; e < EMB; e++) C[e] += w2 * W_sp[j * EMB + e];
    }
    row[H + 0] = a0;
    row[H + 1] = a1;
    for (int c = 0; c < NCELL; c++) {
        float d = 0.f;
        #pragma unroll
        for (int e = 0; e < EMB; e++) d += C[e] * embed[c * EMB + e];
        row[H + 2 + c] = d;
    }
    row[146] = 0.f; row[147] = 0.f;

    float bb = b_ih[g] + b_hh[g] + s1;
    g_bias[g]      = bb + s2;   // obs steps (social bias present)
    g_bias[G4 + g] = bb;        // pred steps (social half is exactly zero)
}

// ---------------- kernel 2: neighbor histogram -> feat ----------------
// idx = clip(floor(rel/0.5), -2, 1) + 2 per coord; flat = ix*4+iy in [0,15]
__global__ void hist_kernel(const float* __restrict__ obs, const float* __restrict__ nbr, int B)
{
    __shared__ int cnt[4][T_OBS][NCELL];
    int w = threadIdx.x >> 5, lane = threadIdx.x & 31;
    int b = blockIdx.x * 4 + w;

    for (int i = threadIdx.x; i < 4 * T_OBS * NCELL; i += blockDim.x)
        ((int*)cnt)[i] = 0;
    __syncthreads();

    if (b < B) {
        float of[16];
        const float4* op = (const float4*)(obs + (size_t)b * T_OBS * 2);
        #pragma unroll
        for (int q = 0; q < 4; q++) {
            float4 v = op[q];
            of[4 * q + 0] = v.x; of[4 * q + 1] = v.y; of[4 * q + 2] = v.z; of[4 * q + 3] = v.w;
        }
        #pragma unroll
        for (int half = 0; half < 2; half++) {
            int nn = lane + half * 32;
            const float4* np = (const float4*)(nbr + ((size_t)b * NNB + nn) * T_OBS * 2);
            float nf[16];
            #pragma unroll
            for (int q = 0; q < 4; q++) {
                float4 v = np[q];
                nf[4 * q + 0] = v.x; nf[4 * q + 1] = v.y; nf[4 * q + 2] = v.z; nf[4 * q + 3] = v.w;
            }
            #pragma unroll
            for (int t = 0; t < T_OBS; t++) {
                float rx = nf[2 * t + 0] - of[2 * t + 0];
                float ry = nf[2 * t + 1] - of[2 * t + 1];
                int ix = (int)floorf(rx * 2.0f);
                int iy = (int)floorf(ry * 2.0f);
                ix = max(-2, min(1, ix)) + 2;
                iy = max(-2, min(1, iy)) + 2;
                atomicAdd(&cnt[w][t][ix * 4 + iy], 1);
            }
        }
    }
    __syncthreads();

    if (b < B) {
        for (int i = lane; i < T_OBS * KF; i += 32) {
            int t = i / KF, c = i % KF;
            float v = (c < 2) ? obs[((size_t)b * T_OBS + t) * 2 + c]
                              : (float)cnt[w][t][c - 2];
            g_feat[((size_t)b * T_OBS + t) * KF + c] = v;
        }
    }
}

// ---------------- kernel 3: fused recurrent LSTM ----------------
// Per CTA: 32 batch rows. sh_x[b][0:128]=h, [128:130]=obs/prev, [130:146]=counts, [146:148]=0.
// gates[b][g] = sum_{k<148} x[b][k] * Wcomb[g][k] + bias[g], then elementwise LSTM.
// c-state lives in registers (stable (b,j)<->thread map across steps/chunks).
__global__ void __launch_bounds__(THREADS_R)
lstm_kernel(const float* __restrict__ W_out, const float* __restrict__ b_out,
            float* __restrict__ out, int B)
{
    extern __shared__ float sm[];
    float* sh_x    = sm;                       // BT*KX       = 4736 floats
    float* sh_W    = sh_x + BT * KX;           // 128*KX      = 18944 floats (one j-chunk: 4 gates x 32 j)
    float* sh_bias = sh_W + 128 * KX;          // 2*G4        = 1024 floats
    float* sh_wout = sh_bias + 2 * G4;         // 2*H + 2     = 258 floats

    const int tid = threadIdx.x;
    const int jt  = tid & 15;       // j-thread 0..15 (j and j+16 within chunk)
    const int btl = tid >> 4;       // b-tile 0..7 (4 rows each)
    const int gb0 = blockIdx.x * BT;
    if (gb0 >= B) return;

    // init shared
    for (int i = tid; i < BT * KX; i += THREADS_R) sh_x[i] = 0.f;
    for (int i = tid; i < 2 * G4; i += THREADS_R) sh_bias[i] = g_bias[i];
    for (int i = tid; i < 2 * H; i += THREADS_R) sh_wout[i] = W_out[i];
    if (tid == 0) { sh_wout[2 * H] = b_out[0]; sh_wout[2 * H + 1] = b_out[1]; }

    // persistent per-thread state: 32 (b,j) pairs, [chunk][i][jj]
    float cst[4][4][2];
    float hnw[4][4][2];
    #pragma unroll
    for (int cc = 0; cc < 4; cc++)
        #pragma unroll
        for (int i = 0; i < 4; i++)
            #pragma unroll
            for (int jj = 0; jj < 2; jj++) cst[cc][i][jj] = 0.f;

    __syncthreads();

    for (int step = 0; step < T_OBS + PRED; step++) {
        const bool isObs = (step < T_OBS);

        // stage small-x features
        if (isObs) {
            for (int i = tid; i < BT * KF; i += THREADS_R) {
                int b = i / KF, c = i % KF;
                sh_x[b * KX + H + c] = g_feat[((size_t)(gb0 + b) * T_OBS + step) * KF + c];
            }
        } else if (step == T_OBS) {
            for (int i = tid; i < BT * KF; i += THREADS_R) {
                int b = i / KF, c = i % KF;
                sh_x[b * KX + H + c] = 0.f;   // prev0 = 0, no counts in pred
            }
        }
        const float* bias = sh_bias + (isObs ? 0 : G4);
        __syncthreads();

        // ---- gates GEMM over 4 j-chunks of 32 ----
        #pragma unroll
        for (int cc = 0; cc < 4; cc++) {
            // load weight tile: rows gate*128 + cc*32 + jl  (contiguous per gate block)
            #pragma unroll
            for (int gate = 0; gate < 4; gate++) {
                const float4* src = (const float4*)(g_Wcomb + ((size_t)(gate * H + cc * 32)) * KX);
                float4* dst = (float4*)(sh_W + gate * 32 * KX);
                for (int q = tid; q < 32 * (KX / 4); q += THREADS_R) dst[q] = src[q];
            }
            __syncthreads();

            float acc[4][2][4];   // [i][jj][gate]
            #pragma unroll
            for (int i = 0; i < 4; i++)
                #pragma unroll
                for (int jj = 0; jj < 2; jj++)
                    #pragma unroll
                    for (int g = 0; g < 4; g++)
                        acc[i][jj][g] = bias[g * H + cc * 32 + jt + jj * 16];

            #pragma unroll 2
            for (int k4 = 0; k4 < KX / 4; k4++) {
                float4 xv[4];
                #pragma unroll
                for (int i = 0; i < 4; i++)
                    xv[i] = *(const float4*)&sh_x[(btl * 4 + i) * KX + k4 * 4];
                #pragma unroll
                for (int jj = 0; jj < 2; jj++) {
                    #pragma unroll
                    for (int g = 0; g < 4; g++) {
                        float4 wv = *(const float4*)&sh_W[(g * 32 + jt + jj * 16) * KX + k4 * 4];
                        #pragma unroll
                        for (int i = 0; i < 4; i++) {
                            acc[i][jj][g] += xv[i].x * wv.x;
                            acc[i][jj][g] += xv[i].y * wv.y;
                            acc[i][jj][g] += xv[i].z * wv.z;
                            acc[i][jj][g] += xv[i].w * wv.w;
                        }
                    }
                }
            }

            // elementwise LSTM update for this chunk's pairs (gate order i,f,g,o)
            #pragma unroll
            for (int i = 0; i < 4; i++)
                #pragma unroll
                for (int jj = 0; jj < 2; jj++) {
                    float gi = acc[i][jj][0];
                    float gf = acc[i][jj][1];
                    float gg = acc[i][jj][2];
                    float go = acc[i][jj][3];
                    float c = cst[cc][i][jj];
                    c = sigf(gf) * c + sigf(gi) * tanhf(gg);
                    cst[cc][i][jj] = c;
                    hnw[cc][i][jj] = sigf(go) * tanhf(c);
                }
            __syncthreads();   // all reads of sh_x/sh_W for this chunk done
        }

        // write new h into sh_x
        #pragma unroll
        for (int cc = 0; cc < 4; cc++)
            #pragma unroll
            for (int i = 0; i < 4; i++)
                #pragma unroll
                for (int jj = 0; jj < 2; jj++)
                    sh_x[(btl * 4 + i) * KX + cc * 32 + jt + jj * 16] = hnw[cc][i][jj];
        __syncthreads();

        // prediction: disp = h @ W_out^T + b_out ; feed back as prev
        if (!isObs) {
            if (tid < BT) {
                int b = tid;
                float d0 = sh_wout[2 * H], d1 = sh_wout[2 * H + 1];
                #pragma unroll 4
                for (int k = 0; k < H; k++) {
                    float hv = sh_x[b * KX + k];
                    d0 += hv * sh_wout[k];
                    d1 += hv * sh_wout[H + k];
                }
                int p = step - T_OBS;
                size_t ob = ((size_t)(gb0 + b) * PRED + p) * 2;
                out[ob]     = d0;
                out[ob + 1] = d1;
                sh_x[b * KX + H]     = d0;   // prev for next step
                sh_x[b * KX + H + 1] = d1;
            }
            __syncthreads();
        }
    }
}

// ---------------- launch ----------------
extern "C" void kernel_launch(void* const* d_in, const int* in_sizes, int n_in,
                              void* d_out, int out_size)
{
    const float* obs   = (const float*)d_in[0];
    const float* nbr   = (const float*)d_in[1];
    const float* embed = (const float*)d_in[2];
    const float* W_in  = (const float*)d_in[3];
    const float* b_in  = (const float*)d_in[4];
    const float* W_sp  = (const float*)d_in[5];
    const float* b_sp  = (const float*)d_in[6];
    const float* W_ih  = (const float*)d_in[7];
    const float* W_hh  = (const float*)d_in[8];
    const float* b_ih  = (const float*)d_in[9];
    const float* b_hh  = (const float*)d_in[10];
    const float* W_out = (const float*)d_in[11];
    const float* b_out = (const float*)d_in[12];
    float* out = (float*)d_out;

    int B = in_sizes[0] / (T_OBS * 2);

    prep_kernel<<<16, 32>>>(W_in, b_in, W_sp, b_sp, W_ih, W_hh, b_ih, b_hh, embed);
    hist_kernel<<<(B + 3) / 4, 128>>>(obs, nbr, B);

    int smem = (BT * KX + 128 * KX + 2 * G4 + 2 * H + 2) * (int)sizeof(float); // ~99.8 KB
    cudaFuncSetAttribute(lstm_kernel, cudaFuncAttributeMaxDynamicSharedMemorySize, smem);
    lstm_kernel<<<B / BT, THREADS_R, smem>>>(W_out, b_out, out, B);
}